// round 3
// baseline (speedup 1.0000x reference)
#include <cuda_runtime.h>
#include <cstdint>

#define BM 64
#define BN 64
#define HD 64
#define SEQ 2048
#define NH 12
#define NB 4

constexpr int KS_STRIDE = 68;  // uints per row (pad -> conflict-free QK B-frag LDS)
constexpr int VS_STRIDE = 72;  // pad -> conflict-free PV B-frag LDS
constexpr int PS_STRIDE = 68;  // pad -> conflict-free PV A-frag LDS
constexpr int SMEM_UINTS = 64 * KS_STRIDE + 64 * VS_STRIDE + 64 * PS_STRIDE;
constexpr int SMEM_BYTES = SMEM_UINTS * 4;  // 53248

__device__ __forceinline__ unsigned f2tf(float f) {
    unsigned u;
    asm("cvt.rna.tf32.f32 %0, %1;" : "=r"(u) : "f"(f));
    return u;
}

__device__ __forceinline__ void mma_m16n8k8(float* c, const unsigned* a, const unsigned* b) {
    asm volatile(
        "mma.sync.aligned.m16n8k8.row.col.f32.tf32.tf32.f32 "
        "{%0,%1,%2,%3}, {%4,%5,%6,%7}, {%8,%9}, {%0,%1,%2,%3};"
        : "+f"(c[0]), "+f"(c[1]), "+f"(c[2]), "+f"(c[3])
        : "r"(a[0]), "r"(a[1]), "r"(a[2]), "r"(a[3]), "r"(b[0]), "r"(b[1]));
}

extern "C" __global__ void __launch_bounds__(128, 2)
fa2_tf32_kernel(const float* __restrict__ q, const float* __restrict__ k,
                const float* __restrict__ v, const float* __restrict__ bias,
                float* __restrict__ out) {
    extern __shared__ unsigned smem[];
    unsigned* Ks = smem;                       // [64][KS_STRIDE] tf32 bits, K[key][d]
    unsigned* Vs = Ks + 64 * KS_STRIDE;        // [64][VS_STRIDE] tf32 bits, V[key][d]
    unsigned* Ps = Vs + 64 * VS_STRIDE;        // [64][PS_STRIDE] tf32 bits, P[qrow][key]

    const int tid  = threadIdx.x;
    const int warp = tid >> 5;
    const int lane = tid & 31;
    const int r  = lane >> 2;   // groupID (row within fragment)
    const int cq = lane & 3;    // threadID in group

    const int h = blockIdx.y;
    const int b = blockIdx.z;
    const int q0 = blockIdx.x * BM;

    const int row0 = q0 + warp * 16 + r;       // first query row of this thread
    // row1 = row0 + 8

    const int rowstride = NH * HD;             // 768 floats between sequence positions
    const float* qrow0 = q + (size_t)(b * SEQ + row0) * rowstride + (size_t)h * HD;
    const float* qrow1 = qrow0 + (size_t)8 * rowstride;
    const float* kbase = k + (size_t)b * SEQ * rowstride + (size_t)h * HD;
    const float* vbase = v + (size_t)b * SEQ * rowstride + (size_t)h * HD;
    const float* bias0 = bias + ((size_t)(b * NH + h)) * SEQ * SEQ + (size_t)row0 * SEQ;
    const float* bias1 = bias0 + (size_t)8 * SEQ;

    // ---- Q fragments (A-layout, tf32), resident in registers for whole kernel ----
    unsigned qa[8][4];
#pragma unroll
    for (int kk = 0; kk < 8; kk++) {
        qa[kk][0] = f2tf(__ldg(&qrow0[kk * 8 + cq]));
        qa[kk][1] = f2tf(__ldg(&qrow1[kk * 8 + cq]));
        qa[kk][2] = f2tf(__ldg(&qrow0[kk * 8 + cq + 4]));
        qa[kk][3] = f2tf(__ldg(&qrow1[kk * 8 + cq + 4]));
    }

    float o[8][4];
#pragma unroll
    for (int n = 0; n < 8; n++) {
        o[n][0] = 0.f; o[n][1] = 0.f; o[n][2] = 0.f; o[n][3] = 0.f;
    }
    float m0 = -1e30f, m1 = -1e30f, l0 = 0.f, l1 = 0.f;

    const float scale = 0.125f;  // 1/sqrt(64)

    unsigned* prow0 = &Ps[(warp * 16 + r) * PS_STRIDE];
    unsigned* prow1 = prow0 + 8 * PS_STRIDE;

    for (int kt = 0; kt < SEQ / BN; kt++) {
        __syncthreads();
        // ---- stage K,V tile (64 keys x 64 d) into smem, converted to tf32 ----
        const float* ksrc = kbase + (size_t)(kt * BN) * rowstride;
        const float* vsrc = vbase + (size_t)(kt * BN) * rowstride;
#pragma unroll
        for (int i = 0; i < 8; i++) {
            int idx = tid + i * 128;       // 0..1023
            int row = idx >> 4;
            int c4  = (idx & 15) << 2;
            float4 k4 = *(const float4*)(ksrc + (size_t)row * rowstride + c4);
            uint4 ku = { f2tf(k4.x), f2tf(k4.y), f2tf(k4.z), f2tf(k4.w) };
            *(uint4*)&Ks[row * KS_STRIDE + c4] = ku;
            float4 v4 = *(const float4*)(vsrc + (size_t)row * rowstride + c4);
            uint4 vu = { f2tf(v4.x), f2tf(v4.y), f2tf(v4.z), f2tf(v4.w) };
            *(uint4*)&Vs[row * VS_STRIDE + c4] = vu;
        }
        __syncthreads();

        // ---- S = Q K^T (each warp: 16x64 scores) ----
        float s[8][4];
#pragma unroll
        for (int n = 0; n < 8; n++) {
            s[n][0] = 0.f; s[n][1] = 0.f; s[n][2] = 0.f; s[n][3] = 0.f;
#pragma unroll
            for (int kk = 0; kk < 8; kk++) {
                unsigned bf[2];
                const unsigned* krow = &Ks[(n * 8 + r) * KS_STRIDE + kk * 8];
                bf[0] = krow[cq];
                bf[1] = krow[cq + 4];
                mma_m16n8k8(s[n], qa[kk], bf);
            }
        }

        // ---- scale + bias (bias loaded directly in C-fragment layout) ----
        const int kc = kt * BN;
#pragma unroll
        for (int n = 0; n < 8; n++) {
            float2 bb0 = *(const float2*)(bias0 + kc + n * 8 + 2 * cq);
            float2 bb1 = *(const float2*)(bias1 + kc + n * 8 + 2 * cq);
            s[n][0] = fmaf(s[n][0], scale, bb0.x);
            s[n][1] = fmaf(s[n][1], scale, bb0.y);
            s[n][2] = fmaf(s[n][2], scale, bb1.x);
            s[n][3] = fmaf(s[n][3], scale, bb1.y);
        }

        // ---- online softmax (rows row0 / row0+8) ----
        float mx0 = s[0][0], mx1 = s[0][2];
#pragma unroll
        for (int n = 0; n < 8; n++) {
            mx0 = fmaxf(mx0, fmaxf(s[n][0], s[n][1]));
            mx1 = fmaxf(mx1, fmaxf(s[n][2], s[n][3]));
        }
        mx0 = fmaxf(mx0, __shfl_xor_sync(0xffffffffu, mx0, 1));
        mx0 = fmaxf(mx0, __shfl_xor_sync(0xffffffffu, mx0, 2));
        mx1 = fmaxf(mx1, __shfl_xor_sync(0xffffffffu, mx1, 1));
        mx1 = fmaxf(mx1, __shfl_xor_sync(0xffffffffu, mx1, 2));

        float mn0 = fmaxf(m0, mx0), mn1 = fmaxf(m1, mx1);
        float a0 = __expf(m0 - mn0), a1 = __expf(m1 - mn1);
        m0 = mn0; m1 = mn1;

        float sm0 = 0.f, sm1 = 0.f;
#pragma unroll
        for (int n = 0; n < 8; n++) {
            s[n][0] = __expf(s[n][0] - mn0);
            s[n][1] = __expf(s[n][1] - mn0);
            s[n][2] = __expf(s[n][2] - mn1);
            s[n][3] = __expf(s[n][3] - mn1);
            sm0 += s[n][0] + s[n][1];
            sm1 += s[n][2] + s[n][3];
            o[n][0] *= a0; o[n][1] *= a0; o[n][2] *= a1; o[n][3] *= a1;
        }
        sm0 += __shfl_xor_sync(0xffffffffu, sm0, 1);
        sm0 += __shfl_xor_sync(0xffffffffu, sm0, 2);
        sm1 += __shfl_xor_sync(0xffffffffu, sm1, 1);
        sm1 += __shfl_xor_sync(0xffffffffu, sm1, 2);
        l0 = l0 * a0 + sm0;
        l1 = l1 * a1 + sm1;

        // ---- stage P (tf32) to warp-private smem (C-frag -> A-frag relayout) ----
#pragma unroll
        for (int n = 0; n < 8; n++) {
            uint2 p0 = { f2tf(s[n][0]), f2tf(s[n][1]) };
            *(uint2*)&prow0[n * 8 + 2 * cq] = p0;
            uint2 p1 = { f2tf(s[n][2]), f2tf(s[n][3]) };
            *(uint2*)&prow1[n * 8 + 2 * cq] = p1;
        }
        __syncwarp();

        // ---- O += P V ----
#pragma unroll
        for (int kk = 0; kk < 8; kk++) {
            unsigned pa[4];
            pa[0] = prow0[kk * 8 + cq];
            pa[1] = prow1[kk * 8 + cq];
            pa[2] = prow0[kk * 8 + cq + 4];
            pa[3] = prow1[kk * 8 + cq + 4];
#pragma unroll
            for (int n = 0; n < 8; n++) {
                unsigned bf[2];
                bf[0] = Vs[(kk * 8 + cq) * VS_STRIDE + n * 8 + r];
                bf[1] = Vs[(kk * 8 + cq + 4) * VS_STRIDE + n * 8 + r];
                mma_m16n8k8(o[n], pa, bf);
            }
        }
    }

    // ---- epilogue: normalize and store ----
    float inv0 = 1.f / l0, inv1 = 1.f / l1;
    float* orow0 = out + (size_t)(b * SEQ + row0) * rowstride + (size_t)h * HD;
    float* orow1 = orow0 + (size_t)8 * rowstride;
#pragma unroll
    for (int n = 0; n < 8; n++) {
        float2 t0 = { o[n][0] * inv0, o[n][1] * inv0 };
        *(float2*)&orow0[n * 8 + 2 * cq] = t0;
        float2 t1 = { o[n][2] * inv1, o[n][3] * inv1 };
        *(float2*)&orow1[n * 8 + 2 * cq] = t1;
    }
}

extern "C" void kernel_launch(void* const* d_in, const int* in_sizes, int n_in,
                              void* d_out, int out_size) {
    const float* q    = (const float*)d_in[0];
    const float* k    = (const float*)d_in[1];
    const float* v    = (const float*)d_in[2];
    const float* bias = (const float*)d_in[3];
    float* out = (float*)d_out;

    cudaFuncSetAttribute(fa2_tf32_kernel,
                         cudaFuncAttributeMaxDynamicSharedMemorySize, SMEM_BYTES);

    dim3 grid(SEQ / BM, NH, NB);
    fa2_tf32_kernel<<<grid, 128, SMEM_BYTES>>>(q, k, v, bias, out);
}

// round 7
// speedup vs baseline: 1.1430x; 1.1430x over previous
#include <cuda_runtime.h>
#include <cstdint>

#define SEQ 2048
#define NH 12
#define NB 4
#define HD 64
#define BM 64
#define BN 64
#define THREADS 128
#define RS (NH * HD)          // 768 floats between seq positions
#define NT (SEQ / BN)         // 32 key tiles

#define KSTR 68               // smem row stride (words) for K tile
#define VSTR 72               // smem row stride (words) for V tile
#define PSTR 68               // smem row stride (words) for P tile
#define KWORDS (64 * KSTR)    // 4352
#define VWORDS (64 * VSTR)    // 4608
#define PWORDS (64 * PSTR)    // 4352
#define SMEM_BYTES ((2 * KWORDS + 2 * VWORDS + PWORDS) * 4)   // 89088

// tf32-rounded copies of K and V (pre-pass output)
#define KV_ELEMS (NB * SEQ * NH * HD)   // 6291456
__device__ __align__(16) float g_kr[KV_ELEMS];
__device__ __align__(16) float g_vr[KV_ELEMS];

__device__ __forceinline__ unsigned f2tf(float f) {
    unsigned u;
    asm("cvt.rna.tf32.f32 %0, %1;" : "=r"(u) : "f"(f));
    return u;
}

__device__ __forceinline__ void mma_m16n8k8(float* c, const unsigned* a, const unsigned* b) {
    asm volatile(
        "mma.sync.aligned.m16n8k8.row.col.f32.tf32.tf32.f32 "
        "{%0,%1,%2,%3}, {%4,%5,%6,%7}, {%8,%9}, {%0,%1,%2,%3};"
        : "+f"(c[0]), "+f"(c[1]), "+f"(c[2]), "+f"(c[3])
        : "r"(a[0]), "r"(a[1]), "r"(a[2]), "r"(a[3]), "r"(b[0]), "r"(b[1]));
}

#define CPA16(dst, src) \
    asm volatile("cp.async.cg.shared.global [%0], [%1], 16;" \
                 :: "r"(dst), "l"(src) : "memory")
#define CPA_COMMIT() asm volatile("cp.async.commit_group;" ::: "memory")
#define CPA_WAIT0()  asm volatile("cp.async.wait_group 0;" ::: "memory")

__device__ __forceinline__ uint32_t smem_u32(const void* p) {
    uint32_t a;
    asm("{ .reg .u64 t; cvta.to.shared.u64 t, %1; cvt.u32.u64 %0, t; }"
        : "=r"(a) : "l"(p));
    return a;
}

// ---- pre-pass: round K,V to tf32 bit patterns (grid covers exactly) ----
__global__ void __launch_bounds__(256)
prepass_kernel(const float* __restrict__ k, const float* __restrict__ v) {
    int i = blockIdx.x * blockDim.x + threadIdx.x;   // float4 index
    float4 a = ((const float4*)k)[i];
    float4 b = ((const float4*)v)[i];
    uint4 ua = make_uint4(f2tf(a.x), f2tf(a.y), f2tf(a.z), f2tf(a.w));
    uint4 ub = make_uint4(f2tf(b.x), f2tf(b.y), f2tf(b.z), f2tf(b.w));
    ((uint4*)g_kr)[i] = ua;
    ((uint4*)g_vr)[i] = ub;
}

extern "C" __global__ void __launch_bounds__(THREADS, 2)
fa2_kernel(const float* __restrict__ q, const float* __restrict__ bias,
           float* __restrict__ out) {
    extern __shared__ __align__(16) unsigned smu[];
    // layout: [K0][K1][V0][V1][Ps]
    const uint32_t sbase = smem_u32(smu);
    unsigned* Ps = smu + 2 * KWORDS + 2 * VWORDS;

    const int tid  = threadIdx.x;
    const int warp = tid >> 5;
    const int lane = tid & 31;
    const int r  = lane >> 2;
    const int cq = lane & 3;

    const int h = blockIdx.y;
    const int b = blockIdx.z;
    const int row0 = blockIdx.x * BM + warp * 16 + r;

    const float* qrow0 = q + (size_t)(b * SEQ + row0) * RS + (size_t)h * HD;
    const float* qrow1 = qrow0 + (size_t)8 * RS;
    const float* kb = g_kr + (size_t)b * SEQ * RS + (size_t)h * HD;
    const float* vb = g_vr + (size_t)b * SEQ * RS + (size_t)h * HD;
    const float* bias0 = bias + ((size_t)(b * NH + h)) * SEQ * SEQ + (size_t)row0 * SEQ;
    const float* bias1 = bias0 + (size_t)8 * SEQ;

    // ---- Q fragments (tf32), resident for whole kernel ----
    unsigned qa[8][4];
#pragma unroll
    for (int kk = 0; kk < 8; kk++) {
        qa[kk][0] = f2tf(__ldg(&qrow0[kk * 8 + cq]));
        qa[kk][1] = f2tf(__ldg(&qrow1[kk * 8 + cq]));
        qa[kk][2] = f2tf(__ldg(&qrow0[kk * 8 + cq + 4]));
        qa[kk][3] = f2tf(__ldg(&qrow1[kk * 8 + cq + 4]));
    }

    float o[8][4];
#pragma unroll
    for (int n = 0; n < 8; n++) { o[n][0] = o[n][1] = o[n][2] = o[n][3] = 0.f; }
    float m0 = -1e30f, m1 = -1e30f, l0 = 0.f, l1 = 0.f;
    const float scale = 0.125f;

    unsigned* prow0 = &Ps[(warp * 16 + r) * PSTR];
    unsigned* prow1 = prow0 + 8 * PSTR;

    // ---- stage tile kt into buffer bsel (cp.async, 16B chunks) ----
    auto stage = [&](int kt, int bsel) {
        const float* ks = kb + (size_t)(kt * BN) * RS;
        const float* vs = vb + (size_t)(kt * BN) * RS;
        uint32_t kdst = sbase + (uint32_t)(bsel * KWORDS) * 4u;
        uint32_t vdst = sbase + (uint32_t)(2 * KWORDS + bsel * VWORDS) * 4u;
#pragma unroll
        for (int i = 0; i < 8; i++) {
            int f = tid + i * 128;
            int row = f >> 4, c4 = (f & 15) << 2;
            CPA16(kdst + (uint32_t)(row * KSTR + c4) * 4u, ks + (size_t)row * RS + c4);
            CPA16(vdst + (uint32_t)(row * VSTR + c4) * 4u, vs + (size_t)row * RS + c4);
        }
        CPA_COMMIT();
    };

    stage(0, 0);

    for (int kt = 0; kt < NT; kt++) {
        // ---- bias prefetch (streaming; issued before the smem wait) ----
        const int kc = kt * BN;
        float br[8][4];
#pragma unroll
        for (int n = 0; n < 8; n++) {
            float2 bb0 = __ldcs((const float2*)(bias0 + kc + n * 8 + 2 * cq));
            float2 bb1 = __ldcs((const float2*)(bias1 + kc + n * 8 + 2 * cq));
            br[n][0] = bb0.x; br[n][1] = bb0.y; br[n][2] = bb1.x; br[n][3] = bb1.y;
        }

        CPA_WAIT0();
        __syncthreads();
        if (kt + 1 < NT) stage(kt + 1, (kt + 1) & 1);

        const unsigned* Ks = smu + (kt & 1) * KWORDS;
        const unsigned* Vs = smu + 2 * KWORDS + (kt & 1) * VWORDS;

        // ---- S = Q K^T ----
        float s[8][4];
#pragma unroll
        for (int n = 0; n < 8; n++) {
            s[n][0] = s[n][1] = s[n][2] = s[n][3] = 0.f;
            const unsigned* krow = &Ks[(n * 8 + r) * KSTR];
#pragma unroll
            for (int kk = 0; kk < 8; kk++) {
                unsigned bf[2];
                bf[0] = krow[kk * 8 + cq];
                bf[1] = krow[kk * 8 + cq + 4];
                mma_m16n8k8(s[n], qa[kk], bf);
            }
        }

        // ---- scale + bias ----
#pragma unroll
        for (int n = 0; n < 8; n++) {
            s[n][0] = fmaf(s[n][0], scale, br[n][0]);
            s[n][1] = fmaf(s[n][1], scale, br[n][1]);
            s[n][2] = fmaf(s[n][2], scale, br[n][2]);
            s[n][3] = fmaf(s[n][3], scale, br[n][3]);
        }

        // ---- online softmax ----
        float mx0 = s[0][0], mx1 = s[0][2];
#pragma unroll
        for (int n = 0; n < 8; n++) {
            mx0 = fmaxf(mx0, fmaxf(s[n][0], s[n][1]));
            mx1 = fmaxf(mx1, fmaxf(s[n][2], s[n][3]));
        }
        mx0 = fmaxf(mx0, __shfl_xor_sync(0xffffffffu, mx0, 1));
        mx0 = fmaxf(mx0, __shfl_xor_sync(0xffffffffu, mx0, 2));
        mx1 = fmaxf(mx1, __shfl_xor_sync(0xffffffffu, mx1, 1));
        mx1 = fmaxf(mx1, __shfl_xor_sync(0xffffffffu, mx1, 2));

        float mn0 = fmaxf(m0, mx0), mn1 = fmaxf(m1, mx1);
        float a0 = __expf(m0 - mn0), a1 = __expf(m1 - mn1);
        m0 = mn0; m1 = mn1;

        float sm0 = 0.f, sm1 = 0.f;
#pragma unroll
        for (int n = 0; n < 8; n++) {
            float p0 = __expf(s[n][0] - mn0);
            float p1 = __expf(s[n][1] - mn0);
            float p2 = __expf(s[n][2] - mn1);
            float p3 = __expf(s[n][3] - mn1);
            sm0 += p0 + p1;
            sm1 += p2 + p3;
            s[n][0] = p0; s[n][1] = p1; s[n][2] = p2; s[n][3] = p3;
            o[n][0] *= a0; o[n][1] *= a0; o[n][2] *= a1; o[n][3] *= a1;
        }
        sm0 += __shfl_xor_sync(0xffffffffu, sm0, 1);
        sm0 += __shfl_xor_sync(0xffffffffu, sm0, 2);
        sm1 += __shfl_xor_sync(0xffffffffu, sm1, 1);
        sm1 += __shfl_xor_sync(0xffffffffu, sm1, 2);
        l0 = l0 * a0 + sm0;
        l1 = l1 * a1 + sm1;

        // ---- stage P (tf32) to warp-private smem (C-frag -> A-frag relayout) ----
#pragma unroll
        for (int n = 0; n < 8; n++) {
            uint2 p0 = { f2tf(s[n][0]), f2tf(s[n][1]) };
            *(uint2*)&prow0[n * 8 + 2 * cq] = p0;
            uint2 p1 = { f2tf(s[n][2]), f2tf(s[n][3]) };
            *(uint2*)&prow1[n * 8 + 2 * cq] = p1;
        }
        __syncwarp();

        // ---- O += P V ----
#pragma unroll
        for (int kk = 0; kk < 8; kk++) {
            unsigned pa[4];
            pa[0] = prow0[kk * 8 + cq];
            pa[1] = prow1[kk * 8 + cq];
            pa[2] = prow0[kk * 8 + cq + 4];
            pa[3] = prow1[kk * 8 + cq + 4];
            const unsigned* vrow0 = &Vs[(kk * 8 + cq) * VSTR];
            const unsigned* vrow1 = &Vs[(kk * 8 + cq + 4) * VSTR];
#pragma unroll
            for (int n = 0; n < 8; n++) {
                unsigned bf[2];
                bf[0] = vrow0[n * 8 + r];
                bf[1] = vrow1[n * 8 + r];
                mma_m16n8k8(o[n], pa, bf);
            }
        }
        __syncwarp();
    }

    // ---- epilogue ----
    float inv0 = 1.f / l0, inv1 = 1.f / l1;
    float* orow0 = out + (size_t)(b * SEQ + row0) * RS + (size_t)h * HD;
    float* orow1 = orow0 + (size_t)8 * RS;
#pragma unroll
    for (int n = 0; n < 8; n++) {
        float2 t0 = { o[n][0] * inv0, o[n][1] * inv0 };
        *(float2*)&orow0[n * 8 + 2 * cq] = t0;
        float2 t1 = { o[n][2] * inv1, o[n][3] * inv1 };
        *(float2*)&orow1[n * 8 + 2 * cq] = t1;
    }
}

extern "C" void kernel_launch(void* const* d_in, const int* in_sizes, int n_in,
                              void* d_out, int out_size) {
    const float* q    = (const float*)d_in[0];
    const float* k    = (const float*)d_in[1];
    const float* v    = (const float*)d_in[2];
    const float* bias = (const float*)d_in[3];
    float* out = (float*)d_out;

    // pre-pass: round K,V to tf32 bit patterns (exact grid cover)
    prepass_kernel<<<KV_ELEMS / 4 / 256, 256>>>(k, v);

    cudaFuncSetAttribute(fa2_kernel,
                         cudaFuncAttributeMaxDynamicSharedMemorySize, SMEM_BYTES);
    dim3 grid(SEQ / BM, NH, NB);
    fa2_kernel<<<grid, THREADS, SMEM_BYTES>>>(q, bias, out);
}

// round 9
// speedup vs baseline: 1.3843x; 1.2112x over previous
#include <cuda_runtime.h>
#include <cuda_fp16.h>
#include <cstdint>

#define SEQ 2048
#define NH 12
#define NB 4
#define HD 64
#define BM 64
#define BN 64
#define THREADS 128
#define RS (NH * HD)          // 768 floats between seq positions
#define NT (SEQ / BN)         // 32 key tiles

#define KSTR 68               // K smem row stride (words)
#define KWORDS (64 * KSTR)    // 4352
#define VHSTR 36              // V^T smem row stride (words) = 72 halves
#define VHWORDS (64 * VHSTR)  // 2304
#define PHWORDS (64 * VHSTR)  // P fp16 tile, same stride
#define SMEM_BYTES ((2 * KWORDS + 2 * VHWORDS + PHWORDS) * 4)   // 62464

#define KV_ELEMS (NB * SEQ * NH * HD)   // 6291456
__device__ __align__(16) float  g_kr[KV_ELEMS];   // tf32-rounded K
__device__ __align__(16) __half g_vh[KV_ELEMS];   // fp16 V, transposed [b][h][d][s]

__device__ __forceinline__ unsigned f2tf(float f) {
    unsigned u;
    asm("cvt.rna.tf32.f32 %0, %1;" : "=r"(u) : "f"(f));
    return u;
}
__device__ __forceinline__ unsigned pack_h2(float lo, float hi) {
    unsigned w;
    asm("cvt.rn.f16x2.f32 %0, %1, %2;" : "=r"(w) : "f"(hi), "f"(lo));
    return w;
}

__device__ __forceinline__ void mma_tf32(float* c, const unsigned* a, const unsigned* b) {
    asm volatile(
        "mma.sync.aligned.m16n8k8.row.col.f32.tf32.tf32.f32 "
        "{%0,%1,%2,%3}, {%4,%5,%6,%7}, {%8,%9}, {%0,%1,%2,%3};"
        : "+f"(c[0]), "+f"(c[1]), "+f"(c[2]), "+f"(c[3])
        : "r"(a[0]), "r"(a[1]), "r"(a[2]), "r"(a[3]), "r"(b[0]), "r"(b[1]));
}
__device__ __forceinline__ void mma_f16(float* c, const unsigned* a, const unsigned* b) {
    asm volatile(
        "mma.sync.aligned.m16n8k16.row.col.f32.f16.f16.f32 "
        "{%0,%1,%2,%3}, {%4,%5,%6,%7}, {%8,%9}, {%0,%1,%2,%3};"
        : "+f"(c[0]), "+f"(c[1]), "+f"(c[2]), "+f"(c[3])
        : "r"(a[0]), "r"(a[1]), "r"(a[2]), "r"(a[3]), "r"(b[0]), "r"(b[1]));
}

#define CPA16(dst, src) \
    asm volatile("cp.async.cg.shared.global [%0], [%1], 16;" \
                 :: "r"(dst), "l"(src) : "memory")
#define CPA_COMMIT() asm volatile("cp.async.commit_group;" ::: "memory")
#define CPA_WAIT0()  asm volatile("cp.async.wait_group 0;" ::: "memory")

__device__ __forceinline__ uint32_t smem_u32(const void* p) {
    uint32_t a;
    asm("{ .reg .u64 t; cvta.to.shared.u64 t, %1; cvt.u32.u64 %0, t; }"
        : "=r"(a) : "l"(p));
    return a;
}

// ---- prepass A: round K to tf32 bit patterns ----
__global__ void __launch_bounds__(256)
prepass_k(const float* __restrict__ k) {
    int i = blockIdx.x * blockDim.x + threadIdx.x;   // float4 index
    float4 a = ((const float4*)k)[i];
    ((uint4*)g_kr)[i] = make_uint4(f2tf(a.x), f2tf(a.y), f2tf(a.z), f2tf(a.w));
}

// ---- prepass B: V -> fp16, transposed to [b][h][d][s] ----
__global__ void __launch_bounds__(256)
prepass_v(const float* __restrict__ v) {
    int i = blockIdx.x * blockDim.x + threadIdx.x;   // NB*NH*16*SEQ threads
    int s  = i & (SEQ - 1);
    int t  = i >> 11;
    int d4 = t & 15;
    int t2 = t >> 4;
    int h  = t2 % NH;
    int b  = t2 / NH;
    float4 val = *(const float4*)(v + ((size_t)(b * SEQ + s) * NH + h) * HD + d4 * 4);
    size_t base = ((size_t)(b * NH + h) * HD + d4 * 4) * SEQ + s;
    g_vh[base + 0 * SEQ] = __float2half_rn(val.x);
    g_vh[base + 1 * SEQ] = __float2half_rn(val.y);
    g_vh[base + 2 * SEQ] = __float2half_rn(val.z);
    g_vh[base + 3 * SEQ] = __float2half_rn(val.w);
}

extern "C" __global__ void __launch_bounds__(THREADS, 2)
fa2_kernel(const float* __restrict__ q, const float* __restrict__ bias,
           float* __restrict__ out) {
    extern __shared__ __align__(16) unsigned smu[];
    // layout (words): [K0][K1][V0][V1][Ph]
    const uint32_t sbase = smem_u32(smu);
    unsigned* Ph = smu + 2 * KWORDS + 2 * VHWORDS;

    const int tid  = threadIdx.x;
    const int warp = tid >> 5;
    const int lane = tid & 31;
    const int r  = lane >> 2;
    const int cq = lane & 3;
    const int wq = warp * 16;

    const int h = blockIdx.y;
    const int b = blockIdx.z;
    const int row0 = blockIdx.x * BM + wq + r;

    const float*  qrow0 = q + (size_t)(b * SEQ + row0) * RS + (size_t)h * HD;
    const float*  qrow1 = qrow0 + (size_t)8 * RS;
    const float*  kb  = g_kr + (size_t)b * SEQ * RS + (size_t)h * HD;
    const __half* vbh = g_vh + (size_t)(b * NH + h) * HD * SEQ;
    const float*  bias0 = bias + ((size_t)(b * NH + h)) * SEQ * SEQ + (size_t)row0 * SEQ;
    const float*  bias1 = bias0 + (size_t)8 * SEQ;

    // ---- Q fragments (tf32), resident for whole kernel ----
    unsigned qa[8][4];
#pragma unroll
    for (int kk = 0; kk < 8; kk++) {
        qa[kk][0] = f2tf(__ldg(&qrow0[kk * 8 + cq]));
        qa[kk][1] = f2tf(__ldg(&qrow1[kk * 8 + cq]));
        qa[kk][2] = f2tf(__ldg(&qrow0[kk * 8 + cq + 4]));
        qa[kk][3] = f2tf(__ldg(&qrow1[kk * 8 + cq + 4]));
    }

    float o[8][4];
#pragma unroll
    for (int n = 0; n < 8; n++) { o[n][0] = o[n][1] = o[n][2] = o[n][3] = 0.f; }
    float m0 = -1e30f, m1 = -1e30f, l0 = 0.f, l1 = 0.f;
    const float scale = 0.125f;

    // ---- stage tile kt into buffer bsel ----
    auto stage = [&](int kt, int bsel) {
        const float*  ks = kb + (size_t)(kt * BN) * RS;
        const __half* vs = vbh + kt * BN;            // column offset; row stride SEQ
        uint32_t kdst = sbase + (uint32_t)(bsel * KWORDS) * 4u;
        uint32_t vdst = sbase + (uint32_t)(2 * KWORDS + bsel * VHWORDS) * 4u;
#pragma unroll
        for (int i = 0; i < 8; i++) {
            int f = tid + i * 128;
            int row = f >> 4, c4 = (f & 15) << 2;
            CPA16(kdst + (uint32_t)(row * KSTR + c4) * 4u, ks + (size_t)row * RS + c4);
        }
#pragma unroll
        for (int i = 0; i < 4; i++) {
            int f = tid + i * 128;          // 0..511
            int row = f >> 3, c16 = f & 7;  // 64 d-rows x 8 chunks of 16B
            CPA16(vdst + (uint32_t)(row * VHSTR + c16 * 4) * 4u,
                  vs + (size_t)row * SEQ + c16 * 8);
        }
        CPA_COMMIT();
    };

    stage(0, 0);

    for (int kt = 0; kt < NT; kt++) {
        // ---- bias prefetch (streaming; issued before the smem wait) ----
        const int kc = kt * BN;
        float br[8][4];
#pragma unroll
        for (int n = 0; n < 8; n++) {
            float2 bb0 = __ldcs((const float2*)(bias0 + kc + n * 8 + 2 * cq));
            float2 bb1 = __ldcs((const float2*)(bias1 + kc + n * 8 + 2 * cq));
            br[n][0] = bb0.x; br[n][1] = bb0.y; br[n][2] = bb1.x; br[n][3] = bb1.y;
        }

        CPA_WAIT0();
        __syncthreads();
        if (kt + 1 < NT) stage(kt + 1, (kt + 1) & 1);

        const unsigned* Ks = smu + (kt & 1) * KWORDS;
        const unsigned* Vw = smu + 2 * KWORDS + (kt & 1) * VHWORDS;

        // ---- S = Q K^T (tf32) ----
        float s[8][4];
#pragma unroll
        for (int n = 0; n < 8; n++) {
            s[n][0] = s[n][1] = s[n][2] = s[n][3] = 0.f;
            const unsigned* krow = &Ks[(n * 8 + r) * KSTR];
#pragma unroll
            for (int kk = 0; kk < 8; kk++) {
                unsigned bf[2];
                bf[0] = krow[kk * 8 + cq];
                bf[1] = krow[kk * 8 + cq + 4];
                mma_tf32(s[n], qa[kk], bf);
            }
        }

        // ---- scale + bias ----
#pragma unroll
        for (int n = 0; n < 8; n++) {
            s[n][0] = fmaf(s[n][0], scale, br[n][0]);
            s[n][1] = fmaf(s[n][1], scale, br[n][1]);
            s[n][2] = fmaf(s[n][2], scale, br[n][2]);
            s[n][3] = fmaf(s[n][3], scale, br[n][3]);
        }

        // ---- online softmax ----
        float mx0 = s[0][0], mx1 = s[0][2];
#pragma unroll
        for (int n = 0; n < 8; n++) {
            mx0 = fmaxf(mx0, fmaxf(s[n][0], s[n][1]));
            mx1 = fmaxf(mx1, fmaxf(s[n][2], s[n][3]));
        }
        mx0 = fmaxf(mx0, __shfl_xor_sync(0xffffffffu, mx0, 1));
        mx0 = fmaxf(mx0, __shfl_xor_sync(0xffffffffu, mx0, 2));
        mx1 = fmaxf(mx1, __shfl_xor_sync(0xffffffffu, mx1, 1));
        mx1 = fmaxf(mx1, __shfl_xor_sync(0xffffffffu, mx1, 2));

        float mn0 = fmaxf(m0, mx0), mn1 = fmaxf(m1, mx1);
        float a0 = __expf(m0 - mn0), a1 = __expf(m1 - mn1);
        m0 = mn0; m1 = mn1;

        float sm0 = 0.f, sm1 = 0.f;
#pragma unroll
        for (int n = 0; n < 8; n++) {
            float p0 = __expf(s[n][0] - mn0);
            float p1 = __expf(s[n][1] - mn0);
            float p2 = __expf(s[n][2] - mn1);
            float p3 = __expf(s[n][3] - mn1);
            sm0 += p0 + p1;
            sm1 += p2 + p3;
            // P -> fp16x2, staged to warp-private smem (C-frag -> A-frag relayout)
            Ph[(wq + r) * VHSTR + n * 4 + cq]     = pack_h2(p0, p1);
            Ph[(wq + r + 8) * VHSTR + n * 4 + cq] = pack_h2(p2, p3);
            o[n][0] *= a0; o[n][1] *= a0; o[n][2] *= a1; o[n][3] *= a1;
        }
        sm0 += __shfl_xor_sync(0xffffffffu, sm0, 1);
        sm0 += __shfl_xor_sync(0xffffffffu, sm0, 2);
        sm1 += __shfl_xor_sync(0xffffffffu, sm1, 1);
        sm1 += __shfl_xor_sync(0xffffffffu, sm1, 2);
        l0 = l0 * a0 + sm0;
        l1 = l1 * a1 + sm1;
        __syncwarp();

        // ---- O += P V (fp16 m16n8k16) ----
#pragma unroll
        for (int kk = 0; kk < 4; kk++) {
            unsigned pa[4];
            const unsigned* pr0 = &Ph[(wq + r) * VHSTR + kk * 8 + cq];
            const unsigned* pr1 = pr0 + 8 * VHSTR;
            pa[0] = pr0[0];
            pa[1] = pr1[0];
            pa[2] = pr0[4];
            pa[3] = pr1[4];
#pragma unroll
            for (int n = 0; n < 8; n++) {
                unsigned bf[2];
                const unsigned* vrow = &Vw[(n * 8 + r) * VHSTR + kk * 8 + cq];
                bf[0] = vrow[0];
                bf[1] = vrow[4];
                mma_f16(o[n], pa, bf);
            }
        }
        __syncwarp();
    }

    // ---- epilogue ----
    float inv0 = 1.f / l0, inv1 = 1.f / l1;
    float* orow0 = out + (size_t)(b * SEQ + row0) * RS + (size_t)h * HD;
    float* orow1 = orow0 + (size_t)8 * RS;
#pragma unroll
    for (int n = 0; n < 8; n++) {
        float2 t0 = { o[n][0] * inv0, o[n][1] * inv0 };
        *(float2*)&orow0[n * 8 + 2 * cq] = t0;
        float2 t1 = { o[n][2] * inv1, o[n][3] * inv1 };
        *(float2*)&orow1[n * 8 + 2 * cq] = t1;
    }
}

extern "C" void kernel_launch(void* const* d_in, const int* in_sizes, int n_in,
                              void* d_out, int out_size) {
    const float* q    = (const float*)d_in[0];
    const float* k    = (const float*)d_in[1];
    const float* v    = (const float*)d_in[2];
    const float* bias = (const float*)d_in[3];
    float* out = (float*)d_out;

    prepass_k<<<KV_ELEMS / 4 / 256, 256>>>(k);
    prepass_v<<<KV_ELEMS / 4 / 256, 256>>>(v);

    cudaFuncSetAttribute(fa2_kernel,
                         cudaFuncAttributeMaxDynamicSharedMemorySize, SMEM_BYTES);
    dim3 grid(SEQ / BM, NH, NB);
    fa2_kernel<<<grid, THREADS, SMEM_BYTES>>>(q, bias, out);
}

// round 10
// speedup vs baseline: 1.8081x; 1.3061x over previous
#include <cuda_runtime.h>
#include <cuda_fp16.h>
#include <cstdint>

#define SEQ 2048
#define NH 12
#define NB 4
#define HD 64
#define BM 64
#define BN 64
#define THREADS 128
#define RS (NH * HD)          // 768 elems between seq positions
#define NT (SEQ / BN)         // 32 key tiles

#define KHSTR 36              // K fp16 smem row stride (words) = 72 halves
#define VHSTR 36              // V^T fp16 smem row stride (words)
#define TWORDS (64 * KHSTR)   // 2304 words per tile buffer
#define SMEM_BYTES (5 * TWORDS * 4)   // K0 K1 V0 V1 Ph = 46080

#define KV_ELEMS (NB * SEQ * NH * HD)   // 6291456
__device__ __align__(16) __half g_kh[KV_ELEMS];   // fp16 K, layout [b][s][h][d]
__device__ __align__(16) __half g_vh[KV_ELEMS];   // fp16 V, transposed [b][h][d][s]

__device__ __forceinline__ unsigned pack_h2(float lo, float hi) {
    unsigned w;
    asm("cvt.rn.f16x2.f32 %0, %1, %2;" : "=r"(w) : "f"(hi), "f"(lo));
    return w;
}

__device__ __forceinline__ void mma_f16(float* c, const unsigned* a, const unsigned* b) {
    asm volatile(
        "mma.sync.aligned.m16n8k16.row.col.f32.f16.f16.f32 "
        "{%0,%1,%2,%3}, {%4,%5,%6,%7}, {%8,%9}, {%0,%1,%2,%3};"
        : "+f"(c[0]), "+f"(c[1]), "+f"(c[2]), "+f"(c[3])
        : "r"(a[0]), "r"(a[1]), "r"(a[2]), "r"(a[3]), "r"(b[0]), "r"(b[1]));
}

#define CPA16(dst, src) \
    asm volatile("cp.async.cg.shared.global [%0], [%1], 16;" \
                 :: "r"(dst), "l"(src) : "memory")
#define CPA_COMMIT() asm volatile("cp.async.commit_group;" ::: "memory")
#define CPA_WAIT0()  asm volatile("cp.async.wait_group 0;" ::: "memory")

__device__ __forceinline__ uint32_t smem_u32(const void* p) {
    uint32_t a;
    asm("{ .reg .u64 t; cvta.to.shared.u64 t, %1; cvt.u32.u64 %0, t; }"
        : "=r"(a) : "l"(p));
    return a;
}

// ---- prepass A: K -> fp16, same layout ----
__global__ void __launch_bounds__(256)
prepass_k(const float* __restrict__ k) {
    int i = blockIdx.x * blockDim.x + threadIdx.x;   // float4 index
    float4 a = ((const float4*)k)[i];
    ((uint2*)g_kh)[i] = make_uint2(pack_h2(a.x, a.y), pack_h2(a.z, a.w));
}

// ---- prepass B: V -> fp16, transposed to [b][h][d][s] ----
__global__ void __launch_bounds__(256)
prepass_v(const float* __restrict__ v) {
    int i = blockIdx.x * blockDim.x + threadIdx.x;   // NB*NH*16*SEQ threads
    int s  = i & (SEQ - 1);
    int t  = i >> 11;
    int d4 = t & 15;
    int t2 = t >> 4;
    int h  = t2 % NH;
    int b  = t2 / NH;
    float4 val = *(const float4*)(v + ((size_t)(b * SEQ + s) * NH + h) * HD + d4 * 4);
    size_t base = ((size_t)(b * NH + h) * HD + d4 * 4) * SEQ + s;
    g_vh[base + 0 * SEQ] = __float2half_rn(val.x);
    g_vh[base + 1 * SEQ] = __float2half_rn(val.y);
    g_vh[base + 2 * SEQ] = __float2half_rn(val.z);
    g_vh[base + 3 * SEQ] = __float2half_rn(val.w);
}

extern "C" __global__ void __launch_bounds__(THREADS, 2)
fa2_kernel(const float* __restrict__ q, const float* __restrict__ bias,
           float* __restrict__ out) {
    extern __shared__ __align__(16) unsigned smu[];
    // layout (words): [K0][K1][V0][V1][Ph]
    const uint32_t sbase = smem_u32(smu);
    unsigned* Ph = smu + 4 * TWORDS;

    const int tid  = threadIdx.x;
    const int warp = tid >> 5;
    const int lane = tid & 31;
    const int r  = lane >> 2;
    const int cq = lane & 3;
    const int wq = warp * 16;

    const int h = blockIdx.y;
    const int b = blockIdx.z;
    const int row0 = blockIdx.x * BM + wq + r;

    const float*  qrow0 = q + (size_t)(b * SEQ + row0) * RS + (size_t)h * HD;
    const float*  qrow1 = qrow0 + (size_t)8 * RS;
    const __half* kb  = g_kh + (size_t)(b * SEQ) * RS + (size_t)h * HD;
    const __half* vbh = g_vh + (size_t)(b * NH + h) * HD * SEQ;
    const float*  bias0 = bias + ((size_t)(b * NH + h)) * SEQ * SEQ + (size_t)row0 * SEQ;
    const float*  bias1 = bias0 + (size_t)8 * SEQ;

    // ---- Q fragments (fp16x2, m16n8k16 A layout), resident for whole kernel ----
    unsigned qa[4][4];
#pragma unroll
    for (int kk = 0; kk < 4; kk++) {
        float2 t00 = *(const float2*)(qrow0 + kk * 16 + 2 * cq);
        float2 t10 = *(const float2*)(qrow1 + kk * 16 + 2 * cq);
        float2 t01 = *(const float2*)(qrow0 + kk * 16 + 2 * cq + 8);
        float2 t11 = *(const float2*)(qrow1 + kk * 16 + 2 * cq + 8);
        qa[kk][0] = pack_h2(t00.x, t00.y);
        qa[kk][1] = pack_h2(t10.x, t10.y);
        qa[kk][2] = pack_h2(t01.x, t01.y);
        qa[kk][3] = pack_h2(t11.x, t11.y);
    }

    float o[8][4];
#pragma unroll
    for (int n = 0; n < 8; n++) { o[n][0] = o[n][1] = o[n][2] = o[n][3] = 0.f; }
    float m0 = -1e30f, m1 = -1e30f, l0 = 0.f, l1 = 0.f;
    const float scale = 0.125f;

    // ---- stage tile kt into buffer bsel ----
    auto stage = [&](int kt, int bsel) {
        const __half* ks = kb + (size_t)(kt * BN) * RS;
        const __half* vs = vbh + kt * BN;            // column offset; row stride SEQ
        uint32_t kdst = sbase + (uint32_t)(bsel * TWORDS) * 4u;
        uint32_t vdst = sbase + (uint32_t)((2 + bsel) * TWORDS) * 4u;
#pragma unroll
        for (int i = 0; i < 4; i++) {
            int f = tid + i * 128;          // 0..511
            int row = f >> 3, c = f & 7;    // 64 rows x 8 chunks of 16B
            CPA16(kdst + (uint32_t)(row * KHSTR + c * 4) * 4u,
                  ks + (size_t)row * RS + c * 8);
            CPA16(vdst + (uint32_t)(row * VHSTR + c * 4) * 4u,
                  vs + (size_t)row * SEQ + c * 8);
        }
        CPA_COMMIT();
    };

    stage(0, 0);

    for (int kt = 0; kt < NT; kt++) {
        // ---- bias prefetch (streaming; issued before the smem wait) ----
        const int kc = kt * BN;
        float br[8][4];
#pragma unroll
        for (int n = 0; n < 8; n++) {
            float2 bb0 = __ldcs((const float2*)(bias0 + kc + n * 8 + 2 * cq));
            float2 bb1 = __ldcs((const float2*)(bias1 + kc + n * 8 + 2 * cq));
            br[n][0] = bb0.x; br[n][1] = bb0.y; br[n][2] = bb1.x; br[n][3] = bb1.y;
        }

        CPA_WAIT0();
        __syncthreads();
        if (kt + 1 < NT) stage(kt + 1, (kt + 1) & 1);

        const unsigned* Kh = smu + (kt & 1) * TWORDS;
        const unsigned* Vw = smu + (2 + (kt & 1)) * TWORDS;

        // ---- S = Q K^T (fp16 m16n8k16) ----
        float s[8][4];
#pragma unroll
        for (int n = 0; n < 8; n++) {
            s[n][0] = s[n][1] = s[n][2] = s[n][3] = 0.f;
            const unsigned* krow = &Kh[(n * 8 + r) * KHSTR];
#pragma unroll
            for (int kk = 0; kk < 4; kk++) {
                unsigned bf[2];
                bf[0] = krow[kk * 8 + cq];
                bf[1] = krow[kk * 8 + cq + 4];
                mma_f16(s[n], qa[kk], bf);
            }
        }

        // ---- scale + bias ----
#pragma unroll
        for (int n = 0; n < 8; n++) {
            s[n][0] = fmaf(s[n][0], scale, br[n][0]);
            s[n][1] = fmaf(s[n][1], scale, br[n][1]);
            s[n][2] = fmaf(s[n][2], scale, br[n][2]);
            s[n][3] = fmaf(s[n][3], scale, br[n][3]);
        }

        // ---- online softmax ----
        float mx0 = s[0][0], mx1 = s[0][2];
#pragma unroll
        for (int n = 0; n < 8; n++) {
            mx0 = fmaxf(mx0, fmaxf(s[n][0], s[n][1]));
            mx1 = fmaxf(mx1, fmaxf(s[n][2], s[n][3]));
        }
        mx0 = fmaxf(mx0, __shfl_xor_sync(0xffffffffu, mx0, 1));
        mx0 = fmaxf(mx0, __shfl_xor_sync(0xffffffffu, mx0, 2));
        mx1 = fmaxf(mx1, __shfl_xor_sync(0xffffffffu, mx1, 1));
        mx1 = fmaxf(mx1, __shfl_xor_sync(0xffffffffu, mx1, 2));

        float mn0 = fmaxf(m0, mx0), mn1 = fmaxf(m1, mx1);
        float a0 = __expf(m0 - mn0), a1 = __expf(m1 - mn1);
        m0 = mn0; m1 = mn1;

        float sm0 = 0.f, sm1 = 0.f;
#pragma unroll
        for (int n = 0; n < 8; n++) {
            float p0 = __expf(s[n][0] - mn0);
            float p1 = __expf(s[n][1] - mn0);
            float p2 = __expf(s[n][2] - mn1);
            float p3 = __expf(s[n][3] - mn1);
            sm0 += p0 + p1;
            sm1 += p2 + p3;
            // P -> fp16x2, staged to warp-private smem (C-frag -> A-frag relayout)
            Ph[(wq + r) * VHSTR + n * 4 + cq]     = pack_h2(p0, p1);
            Ph[(wq + r + 8) * VHSTR + n * 4 + cq] = pack_h2(p2, p3);
            o[n][0] *= a0; o[n][1] *= a0; o[n][2] *= a1; o[n][3] *= a1;
        }
        sm0 += __shfl_xor_sync(0xffffffffu, sm0, 1);
        sm0 += __shfl_xor_sync(0xffffffffu, sm0, 2);
        sm1 += __shfl_xor_sync(0xffffffffu, sm1, 1);
        sm1 += __shfl_xor_sync(0xffffffffu, sm1, 2);
        l0 = l0 * a0 + sm0;
        l1 = l1 * a1 + sm1;
        __syncwarp();

        // ---- O += P V (fp16 m16n8k16) ----
#pragma unroll
        for (int kk = 0; kk < 4; kk++) {
            unsigned pa[4];
            const unsigned* pr0 = &Ph[(wq + r) * VHSTR + kk * 8 + cq];
            const unsigned* pr1 = pr0 + 8 * VHSTR;
            pa[0] = pr0[0];
            pa[1] = pr1[0];
            pa[2] = pr0[4];
            pa[3] = pr1[4];
#pragma unroll
            for (int n = 0; n < 8; n++) {
                unsigned bf[2];
                const unsigned* vrow = &Vw[(n * 8 + r) * VHSTR + kk * 8 + cq];
                bf[0] = vrow[0];
                bf[1] = vrow[4];
                mma_f16(o[n], pa, bf);
            }
        }
        __syncwarp();
    }

    // ---- epilogue ----
    float inv0 = 1.f / l0, inv1 = 1.f / l1;
    float* orow0 = out + (size_t)(b * SEQ + row0) * RS + (size_t)h * HD;
    float* orow1 = orow0 + (size_t)8 * RS;
#pragma unroll
    for (int n = 0; n < 8; n++) {
        float2 t0 = { o[n][0] * inv0, o[n][1] * inv0 };
        *(float2*)&orow0[n * 8 + 2 * cq] = t0;
        float2 t1 = { o[n][2] * inv1, o[n][3] * inv1 };
        *(float2*)&orow1[n * 8 + 2 * cq] = t1;
    }
}

extern "C" void kernel_launch(void* const* d_in, const int* in_sizes, int n_in,
                              void* d_out, int out_size) {
    const float* q    = (const float*)d_in[0];
    const float* k    = (const float*)d_in[1];
    const float* v    = (const float*)d_in[2];
    const float* bias = (const float*)d_in[3];
    float* out = (float*)d_out;

    prepass_k<<<KV_ELEMS / 4 / 256, 256>>>(k);
    prepass_v<<<KV_ELEMS / 4 / 256, 256>>>(v);

    cudaFuncSetAttribute(fa2_kernel,
                         cudaFuncAttributeMaxDynamicSharedMemorySize, SMEM_BYTES);
    dim3 grid(SEQ / BM, NH, NB);
    fa2_kernel<<<grid, THREADS, SMEM_BYTES>>>(q, bias, out);
}

// round 12
// speedup vs baseline: 1.9130x; 1.0580x over previous
#include <cuda_runtime.h>
#include <cuda_fp16.h>
#include <cstdint>

#define SEQ 2048
#define NH 12
#define NB 4
#define HD 64
#define BM 64
#define BN 64
#define THREADS 128
#define RS (NH * HD)          // 768 elems between seq positions
#define NT (SEQ / BN)         // 32 key tiles

#define KHSTR 36              // K fp16 smem row stride (words) = 72 halves
#define VHSTR 36              // V^T fp16 smem row stride (words)
#define TWORDS (64 * KHSTR)   // 2304 words per tile buffer
#define SMEM_BYTES (4 * TWORDS * 4)   // K0 K1 V0 V1 = 36864

#define KV_ELEMS (NB * SEQ * NH * HD)   // 6291456
__device__ __align__(16) __half g_kh[KV_ELEMS];   // fp16 K, layout [b][s][h][d]
__device__ __align__(16) __half g_vh[KV_ELEMS];   // fp16 V, transposed [b][h][d][s]

__device__ __forceinline__ unsigned pack_h2(float lo, float hi) {
    unsigned w;
    asm("cvt.rn.f16x2.f32 %0, %1, %2;" : "=r"(w) : "f"(hi), "f"(lo));
    return w;
}

__device__ __forceinline__ void mma_f16(float* c, const unsigned* a, const unsigned* b) {
    asm volatile(
        "mma.sync.aligned.m16n8k16.row.col.f32.f16.f16.f32 "
        "{%0,%1,%2,%3}, {%4,%5,%6,%7}, {%8,%9}, {%0,%1,%2,%3};"
        : "+f"(c[0]), "+f"(c[1]), "+f"(c[2]), "+f"(c[3])
        : "r"(a[0]), "r"(a[1]), "r"(a[2]), "r"(a[3]), "r"(b[0]), "r"(b[1]));
}

#define CPA16(dst, src) \
    asm volatile("cp.async.cg.shared.global [%0], [%1], 16;" \
                 :: "r"(dst), "l"(src) : "memory")
#define CPA_COMMIT() asm volatile("cp.async.commit_group;" ::: "memory")
#define CPA_WAIT0()  asm volatile("cp.async.wait_group 0;" ::: "memory")

__device__ __forceinline__ uint32_t smem_u32(const void* p) {
    uint32_t a;
    asm("{ .reg .u64 t; cvta.to.shared.u64 t, %1; cvt.u32.u64 %0, t; }"
        : "=r"(a) : "l"(p));
    return a;
}

// ---- prepass A: K -> fp16, same layout ----
__global__ void __launch_bounds__(256)
prepass_k(const float* __restrict__ k) {
    int i = blockIdx.x * blockDim.x + threadIdx.x;   // float4 index
    float4 a = ((const float4*)k)[i];
    ((uint2*)g_kh)[i] = make_uint2(pack_h2(a.x, a.y), pack_h2(a.z, a.w));
}

// ---- prepass B: V -> fp16, transposed to [b][h][d][s] ----
__global__ void __launch_bounds__(256)
prepass_v(const float* __restrict__ v) {
    int i = blockIdx.x * blockDim.x + threadIdx.x;   // NB*NH*16*SEQ threads
    int s  = i & (SEQ - 1);
    int t  = i >> 11;
    int d4 = t & 15;
    int t2 = t >> 4;
    int h  = t2 % NH;
    int b  = t2 / NH;
    float4 val = *(const float4*)(v + ((size_t)(b * SEQ + s) * NH + h) * HD + d4 * 4);
    size_t base = ((size_t)(b * NH + h) * HD + d4 * 4) * SEQ + s;
    g_vh[base + 0 * SEQ] = __float2half_rn(val.x);
    g_vh[base + 1 * SEQ] = __float2half_rn(val.y);
    g_vh[base + 2 * SEQ] = __float2half_rn(val.z);
    g_vh[base + 3 * SEQ] = __float2half_rn(val.w);
}

extern "C" __global__ void __launch_bounds__(THREADS, 3)
fa2_kernel(const float* __restrict__ q, const float* __restrict__ bias,
           float* __restrict__ out) {
    extern __shared__ __align__(16) unsigned smu[];
    // layout (words): [K0][K1][V0][V1]
    const uint32_t sbase = smem_u32(smu);

    const int tid  = threadIdx.x;
    const int warp = tid >> 5;
    const int lane = tid & 31;
    const int r  = lane >> 2;
    const int cq = lane & 3;
    const int wq = warp * 16;

    const int h = blockIdx.y;
    const int b = blockIdx.z;
    const int row0 = blockIdx.x * BM + wq + r;

    const float*  qrow0 = q + (size_t)(b * SEQ + row0) * RS + (size_t)h * HD;
    const float*  qrow1 = qrow0 + (size_t)8 * RS;
    const __half* kb  = g_kh + (size_t)(b * SEQ) * RS + (size_t)h * HD;
    const __half* vbh = g_vh + (size_t)(b * NH + h) * HD * SEQ;
    const float*  bias0 = bias + ((size_t)(b * NH + h)) * SEQ * SEQ + (size_t)row0 * SEQ;
    const float*  bias1 = bias0 + (size_t)8 * SEQ;

    // ---- Q fragments (fp16x2, m16n8k16 A layout), resident for whole kernel ----
    unsigned qa[4][4];
#pragma unroll
    for (int kk = 0; kk < 4; kk++) {
        float2 t00 = *(const float2*)(qrow0 + kk * 16 + 2 * cq);
        float2 t10 = *(const float2*)(qrow1 + kk * 16 + 2 * cq);
        float2 t01 = *(const float2*)(qrow0 + kk * 16 + 2 * cq + 8);
        float2 t11 = *(const float2*)(qrow1 + kk * 16 + 2 * cq + 8);
        qa[kk][0] = pack_h2(t00.x, t00.y);
        qa[kk][1] = pack_h2(t10.x, t10.y);
        qa[kk][2] = pack_h2(t01.x, t01.y);
        qa[kk][3] = pack_h2(t11.x, t11.y);
    }

    float o[8][4];
#pragma unroll
    for (int n = 0; n < 8; n++) { o[n][0] = o[n][1] = o[n][2] = o[n][3] = 0.f; }
    float m0 = -1e30f, m1 = -1e30f, l0 = 0.f, l1 = 0.f;
    const float scale = 0.125f;

    // ---- stage tile kt into buffer bsel ----
    auto stage = [&](int kt, int bsel) {
        const __half* ks = kb + (size_t)(kt * BN) * RS;
        const __half* vs = vbh + kt * BN;            // column offset; row stride SEQ
        uint32_t kdst = sbase + (uint32_t)(bsel * TWORDS) * 4u;
        uint32_t vdst = sbase + (uint32_t)((2 + bsel) * TWORDS) * 4u;
#pragma unroll
        for (int i = 0; i < 4; i++) {
            int f = tid + i * 128;          // 0..511
            int row = f >> 3, c = f & 7;    // 64 rows x 8 chunks of 16B
            CPA16(kdst + (uint32_t)(row * KHSTR + c * 4) * 4u,
                  ks + (size_t)row * RS + c * 8);
            CPA16(vdst + (uint32_t)(row * VHSTR + c * 4) * 4u,
                  vs + (size_t)row * SEQ + c * 8);
        }
        CPA_COMMIT();
    };

    stage(0, 0);

    for (int kt = 0; kt < NT; kt++) {
        // ---- bias prefetch (streaming; issued before the smem wait) ----
        const int kc = kt * BN;
        float br[8][4];
#pragma unroll
        for (int n = 0; n < 8; n++) {
            float2 bb0 = __ldcs((const float2*)(bias0 + kc + n * 8 + 2 * cq));
            float2 bb1 = __ldcs((const float2*)(bias1 + kc + n * 8 + 2 * cq));
            br[n][0] = bb0.x; br[n][1] = bb0.y; br[n][2] = bb1.x; br[n][3] = bb1.y;
        }

        CPA_WAIT0();
        __syncthreads();
        if (kt + 1 < NT) stage(kt + 1, (kt + 1) & 1);

        const unsigned* Kh = smu + (kt & 1) * TWORDS;
        const unsigned* Vw = smu + (2 + (kt & 1)) * TWORDS;

        // ---- S = Q K^T (fp16 m16n8k16) ----
        float s[8][4];
#pragma unroll
        for (int n = 0; n < 8; n++) {
            s[n][0] = s[n][1] = s[n][2] = s[n][3] = 0.f;
            const unsigned* krow = &Kh[(n * 8 + r) * KHSTR];
#pragma unroll
            for (int kk = 0; kk < 4; kk++) {
                unsigned bf[2];
                bf[0] = krow[kk * 8 + cq];
                bf[1] = krow[kk * 8 + cq + 4];
                mma_f16(s[n], qa[kk], bf);
            }
        }

        // ---- scale + bias ----
#pragma unroll
        for (int n = 0; n < 8; n++) {
            s[n][0] = fmaf(s[n][0], scale, br[n][0]);
            s[n][1] = fmaf(s[n][1], scale, br[n][1]);
            s[n][2] = fmaf(s[n][2], scale, br[n][2]);
            s[n][3] = fmaf(s[n][3], scale, br[n][3]);
        }

        // ---- online softmax ----
        float mx0 = s[0][0], mx1 = s[0][2];
#pragma unroll
        for (int n = 0; n < 8; n++) {
            mx0 = fmaxf(mx0, fmaxf(s[n][0], s[n][1]));
            mx1 = fmaxf(mx1, fmaxf(s[n][2], s[n][3]));
        }
        mx0 = fmaxf(mx0, __shfl_xor_sync(0xffffffffu, mx0, 1));
        mx0 = fmaxf(mx0, __shfl_xor_sync(0xffffffffu, mx0, 2));
        mx1 = fmaxf(mx1, __shfl_xor_sync(0xffffffffu, mx1, 1));
        mx1 = fmaxf(mx1, __shfl_xor_sync(0xffffffffu, mx1, 2));

        float mn0 = fmaxf(m0, mx0), mn1 = fmaxf(m1, mx1);
        float a0 = __expf(m0 - mn0), a1 = __expf(m1 - mn1);
        m0 = mn0; m1 = mn1;

        float sm0 = 0.f, sm1 = 0.f;
#pragma unroll
        for (int n = 0; n < 8; n++) {
            float p0 = __expf(s[n][0] - mn0);
            float p1 = __expf(s[n][1] - mn0);
            float p2 = __expf(s[n][2] - mn1);
            float p3 = __expf(s[n][3] - mn1);
            sm0 += p0 + p1;
            sm1 += p2 + p3;
            s[n][0] = p0; s[n][1] = p1; s[n][2] = p2; s[n][3] = p3;
            o[n][0] *= a0; o[n][1] *= a0; o[n][2] *= a1; o[n][3] *= a1;
        }
        sm0 += __shfl_xor_sync(0xffffffffu, sm0, 1);
        sm0 += __shfl_xor_sync(0xffffffffu, sm0, 2);
        sm1 += __shfl_xor_sync(0xffffffffu, sm1, 1);
        sm1 += __shfl_xor_sync(0xffffffffu, sm1, 2);
        l0 = l0 * a0 + sm0;
        l1 = l1 * a1 + sm1;

        // ---- O += P V (fp16 m16n8k16); P A-frags come straight from S C-frags ----
#pragma unroll
        for (int kk = 0; kk < 4; kk++) {
            unsigned pa[4];
            pa[0] = pack_h2(s[2 * kk][0],     s[2 * kk][1]);      // row r,   keys 16kk+2cq,+1
            pa[1] = pack_h2(s[2 * kk][2],     s[2 * kk][3]);      // row r+8, keys 16kk+2cq,+1
            pa[2] = pack_h2(s[2 * kk + 1][0], s[2 * kk + 1][1]);  // row r,   keys 16kk+8+2cq,+1
            pa[3] = pack_h2(s[2 * kk + 1][2], s[2 * kk + 1][3]);  // row r+8, keys 16kk+8+2cq,+1
#pragma unroll
            for (int n = 0; n < 8; n++) {
                unsigned bf[2];
                const unsigned* vrow = &Vw[(n * 8 + r) * VHSTR + kk * 8 + cq];
                bf[0] = vrow[0];
                bf[1] = vrow[4];
                mma_f16(o[n], pa, bf);
            }
        }
    }

    // ---- epilogue ----
    float inv0 = 1.f / l0, inv1 = 1.f / l1;
    float* orow0 = out + (size_t)(b * SEQ + row0) * RS + (size_t)h * HD;
    float* orow1 = orow0 + (size_t)8 * RS;
#pragma unroll
    for (int n = 0; n < 8; n++) {
        float2 t0 = { o[n][0] * inv0, o[n][1] * inv0 };
        *(float2*)&orow0[n * 8 + 2 * cq] = t0;
        float2 t1 = { o[n][2] * inv1, o[n][3] * inv1 };
        *(float2*)&orow1[n * 8 + 2 * cq] = t1;
    }
}

extern "C" void kernel_launch(void* const* d_in, const int* in_sizes, int n_in,
                              void* d_out, int out_size) {
    const float* q    = (const float*)d_in[0];
    const float* k    = (const float*)d_in[1];
    const float* v    = (const float*)d_in[2];
    const float* bias = (const float*)d_in[3];
    float* out = (float*)d_out;

    prepass_k<<<KV_ELEMS / 4 / 256, 256>>>(k);
    prepass_v<<<KV_ELEMS / 4 / 256, 256>>>(v);

    cudaFuncSetAttribute(fa2_kernel,
                         cudaFuncAttributeMaxDynamicSharedMemorySize, SMEM_BYTES);
    dim3 grid(SEQ / BM, NH, NB);
    fa2_kernel<<<grid, THREADS, SMEM_BYTES>>>(q, bias, out);
}